// round 6
// baseline (speedup 1.0000x reference)
#include <cuda_runtime.h>

// Closed form (derived R0): theta_i = x[b,i]+w[i], c_i = cos(2*theta_i)
//   out[b] = { c1*c2*c3, c0*c1, c0*c1*c2, c0*c1*c2*c3 }
//
// R6: data-path pivot. Per-thread LDG (bursty MLP=4, scoreboard-bound) ->
// cp.async/LDGSTS staging: 8x16B async copies per thread issued up front
// (deep MLP, no data registers), private smem slots (no barriers), sliding
// cp.async.wait_group so compute/store of item k overlaps items k+1..7.

#define NTHREADS 256
#define ITEMS    8
#define TOTAL    2097152                        // BATCH (float4 count)
#define NBLOCKS  (TOTAL / (NTHREADS * ITEMS))   // 1024

__device__ __forceinline__ float4 proc(float4 xv, float w0, float w1,
                                       float w2, float w3)
{
    float c0 = __cosf(fmaf(2.0f, xv.x, w0));
    float c1 = __cosf(fmaf(2.0f, xv.y, w1));
    float c2 = __cosf(fmaf(2.0f, xv.z, w2));
    float c3 = __cosf(fmaf(2.0f, xv.w, w3));
    float t01  = c0 * c1;
    float t012 = t01 * c2;
    float4 o;
    o.x = c1 * c2 * c3;
    o.y = t01;
    o.z = t012;
    o.w = t012 * c3;
    return o;
}

__global__ void __launch_bounds__(NTHREADS, 7)
hilbert_cpasync(const float4* __restrict__ x4,
                const float* __restrict__ w,
                float4* __restrict__ out4)
{
    __shared__ float4 sb[NTHREADS * ITEMS];    // 32 KB; slot k*NTHREADS+tx is
                                               // private to thread tx

    int tx   = threadIdx.x;
    int base = blockIdx.x * (NTHREADS * ITEMS);

    float w0 = 2.0f * w[0], w1 = 2.0f * w[1];
    float w2 = 2.0f * w[2], w3 = 2.0f * w[3];

    unsigned sbase;
    {
        unsigned long long g = __cvta_generic_to_shared(&sb[tx]);
        sbase = (unsigned)g;
    }

    // ---- issue all 8 async copies (one commit group each) ----
#define ISSUE(k)                                                          \
    asm volatile("cp.async.cg.shared.global [%0], [%1], 16;\n\t"          \
                 "cp.async.commit_group;\n"                               \
                 :: "r"(sbase + (k) * (NTHREADS * 16)),                   \
                    "l"(x4 + base + (k) * NTHREADS + tx) : "memory");
    ISSUE(0) ISSUE(1) ISSUE(2) ISSUE(3)
    ISSUE(4) ISSUE(5) ISSUE(6) ISSUE(7)
#undef ISSUE

    // ---- consume with sliding wait: item k ready when <= 7-k groups pend ----
#define CONSUME(k, pend)                                                  \
    {                                                                     \
        asm volatile("cp.async.wait_group %0;" :: "n"(pend) : "memory");  \
        float4 v = sb[(k) * NTHREADS + tx];                               \
        out4[base + (k) * NTHREADS + tx] = proc(v, w0, w1, w2, w3);       \
    }
    CONSUME(0, 7) CONSUME(1, 6) CONSUME(2, 5) CONSUME(3, 4)
    CONSUME(4, 3) CONSUME(5, 2) CONSUME(6, 1) CONSUME(7, 0)
#undef CONSUME
}

// Generic fallback (any n of float4s).
__global__ void __launch_bounds__(256)
hilbert_generic(const float4* __restrict__ x4,
                const float* __restrict__ w,
                float4* __restrict__ out4, int n)
{
    int i = blockIdx.x * blockDim.x + threadIdx.x;
    if (i >= n) return;
    float w0 = 2.0f * w[0], w1 = 2.0f * w[1];
    float w2 = 2.0f * w[2], w3 = 2.0f * w[3];
    out4[i] = proc(x4[i], w0, w1, w2, w3);
}

extern "C" void kernel_launch(void* const* d_in, const int* in_sizes, int n_in,
                              void* d_out, int out_size)
{
    const float* x = (const float*)d_in[0];
    const float* w = (const float*)d_in[1];
    int nx = in_sizes[0];
    if (n_in >= 2 && in_sizes[0] < in_sizes[1]) {
        x = (const float*)d_in[1];
        w = (const float*)d_in[0];
        nx = in_sizes[1];
    }

    int n = nx / 4;  // float4 count (= batch)

    if (n == TOTAL) {
        hilbert_cpasync<<<NBLOCKS, NTHREADS>>>(
            (const float4*)x, w, (float4*)d_out);
    } else {
        int threads = 256;
        int blocks = (n + threads - 1) / threads;
        hilbert_generic<<<blocks, threads>>>(
            (const float4*)x, w, (float4*)d_out, n);
    }
}